// round 6
// baseline (speedup 1.0000x reference)
#include <cuda_runtime.h>
#include <cuda_bf16.h>

#define N 4096
#define D 256
#define NBLK 32            // 4096/128 column/row tiles
#define NSLOT 64           // 32 col-blocks * 2 n-warps

static __constant__ float c_dummy; // (nothing)

__device__ __align__(16) __nv_bfloat16 g_fnb[(size_t)N * D];  // normalized features, bf16 (2 MB)
__device__ float g_part[3][NSLOT][N];                         // per-(colslot,row) partials: S1, P, NEG (3 MB)
__device__ float g_bsum[16];                                  // block partial sums of row terms

__device__ __forceinline__ void ldsm_x4(unsigned &r0, unsigned &r1, unsigned &r2, unsigned &r3, unsigned addr) {
    asm volatile("ldmatrix.sync.aligned.m8n8.x4.shared.b16 {%0,%1,%2,%3}, [%4];"
                 : "=r"(r0), "=r"(r1), "=r"(r2), "=r"(r3) : "r"(addr));
}

__device__ __forceinline__ void mma_bf16(float &c0, float &c1, float &c2, float &c3,
                                         unsigned a0, unsigned a1, unsigned a2, unsigned a3,
                                         unsigned b0, unsigned b1) {
    asm volatile("mma.sync.aligned.m16n8k16.row.col.f32.bf16.bf16.f32 "
                 "{%0,%1,%2,%3},{%4,%5,%6,%7},{%8,%9},{%0,%1,%2,%3};"
                 : "+f"(c0), "+f"(c1), "+f"(c2), "+f"(c3)
                 : "r"(a0), "r"(a1), "r"(a2), "r"(a3), "r"(b0), "r"(b1));
}

// ---------------------------------------------------------------------------
// Kernel 1: L2-normalize rows of features, store as bf16. 1 warp per row.
// ---------------------------------------------------------------------------
__global__ __launch_bounds__(128) void norm_kernel(const float* __restrict__ f) {
    const int warp = threadIdx.x >> 5;
    const int lane = threadIdx.x & 31;
    const int row  = blockIdx.x * 4 + warp;

    const float4* fr = reinterpret_cast<const float4*>(f + (size_t)row * D) + lane * 2;
    float4 v0 = fr[0];
    float4 v1 = fr[1];

    float s = v0.x*v0.x + v0.y*v0.y + v0.z*v0.z + v0.w*v0.w
            + v1.x*v1.x + v1.y*v1.y + v1.z*v1.z + v1.w*v1.w;
    #pragma unroll
    for (int off = 16; off > 0; off >>= 1)
        s += __shfl_xor_sync(0xffffffffu, s, off);

    float inv = 1.0f / fmaxf(sqrtf(s), 1e-8f);

    __nv_bfloat162 b0 = __float22bfloat162_rn(make_float2(v0.x*inv, v0.y*inv));
    __nv_bfloat162 b1 = __float22bfloat162_rn(make_float2(v0.z*inv, v0.w*inv));
    __nv_bfloat162 b2 = __float22bfloat162_rn(make_float2(v1.x*inv, v1.y*inv));
    __nv_bfloat162 b3 = __float22bfloat162_rn(make_float2(v1.z*inv, v1.w*inv));

    uint4 u;
    u.x = *reinterpret_cast<unsigned*>(&b0);
    u.y = *reinterpret_cast<unsigned*>(&b1);
    u.z = *reinterpret_cast<unsigned*>(&b2);
    u.w = *reinterpret_cast<unsigned*>(&b3);
    *reinterpret_cast<uint4*>(g_fnb + (size_t)row * D + lane * 8) = u;
}

// ---------------------------------------------------------------------------
// Kernel 2: fused cosim-GEMM (bf16 mma.sync) + mask epilogue.
// Block tile 128x128, 8 warps (4 M x 2 N), warp tile 32x64, K=256 in 4x64 chunks.
// ---------------------------------------------------------------------------
__global__ __launch_bounds__(256) void main_kernel(const float* __restrict__ pm,
                                                   const float* __restrict__ nm) {
    __shared__ __align__(16) __nv_bfloat16 As[128 * 72];
    __shared__ __align__(16) __nv_bfloat16 Bs[128 * 72];

    const int tid   = threadIdx.x;
    const int lane  = tid & 31;
    const int warp  = tid >> 5;
    const int warpM = warp >> 1;   // 0..3
    const int warpN = warp & 1;    // 0..1
    const int rowBase = blockIdx.y * 128;
    const int colBase = blockIdx.x * 128;

    float acc[2][8][4];
    #pragma unroll
    for (int i = 0; i < 2; ++i)
        #pragma unroll
        for (int j = 0; j < 8; ++j)
            #pragma unroll
            for (int k = 0; k < 4; ++k) acc[i][j][k] = 0.f;

    // gmem -> smem mapping: 2 threads per tile-row, 64B each
    const int ldRow = tid >> 1;           // 0..127
    const int ldK   = (tid & 1) * 32;     // 0 / 32 (bf16 units)
    const uint4* fA = reinterpret_cast<const uint4*>(g_fnb + (size_t)(rowBase + ldRow) * D);
    const uint4* fB = reinterpret_cast<const uint4*>(g_fnb + (size_t)(colBase + ldRow) * D);

    const unsigned sA = (unsigned)__cvta_generic_to_shared(As);
    const unsigned sB = (unsigned)__cvta_generic_to_shared(Bs);

    // ldmatrix per-lane address components
    const int aRow = (lane & 7) + ((lane & 8)  ? 8 : 0);
    const int aK8  = (lane & 16) ? 8 : 0;
    const int bRow = (lane & 7) + ((lane & 16) ? 8 : 0);
    const int bK8  = (lane & 8)  ? 8 : 0;

    #pragma unroll 1
    for (int kb = 0; kb < 4; ++kb) {
        __syncthreads();
        #pragma unroll
        for (int c = 0; c < 4; ++c) {
            const int u = kb * 8 + (ldK >> 3) + c;  // uint4 index within row
            *reinterpret_cast<uint4*>(&As[ldRow * 72 + ldK + c * 8]) = fA[u];
            *reinterpret_cast<uint4*>(&Bs[ldRow * 72 + ldK + c * 8]) = fB[u];
        }
        __syncthreads();

        #pragma unroll
        for (int kk = 0; kk < 4; ++kk) {
            unsigned b[4][4];
            #pragma unroll
            for (int p = 0; p < 4; ++p) {
                unsigned addr = sB + ((warpN * 64 + p * 16 + bRow) * 72 + kk * 16 + bK8) * 2;
                ldsm_x4(b[p][0], b[p][1], b[p][2], b[p][3], addr);
            }
            unsigned a[2][4];
            #pragma unroll
            for (int mt = 0; mt < 2; ++mt) {
                unsigned addr = sA + ((warpM * 32 + mt * 16 + aRow) * 72 + kk * 16 + aK8) * 2;
                ldsm_x4(a[mt][0], a[mt][1], a[mt][2], a[mt][3], addr);
            }
            #pragma unroll
            for (int mt = 0; mt < 2; ++mt)
                #pragma unroll
                for (int p = 0; p < 4; ++p) {
                    mma_bf16(acc[mt][2*p  ][0], acc[mt][2*p  ][1], acc[mt][2*p  ][2], acc[mt][2*p  ][3],
                             a[mt][0], a[mt][1], a[mt][2], a[mt][3], b[p][0], b[p][1]);
                    mma_bf16(acc[mt][2*p+1][0], acc[mt][2*p+1][1], acc[mt][2*p+1][2], acc[mt][2*p+1][3],
                             a[mt][0], a[mt][1], a[mt][2], a[mt][3], b[p][2], b[p][3]);
                }
        }
    }

    // ---- epilogue: stream masks, accumulate per-row S1 / P / NEG ----
    const float INV_T = 1.0f / 0.07f;
    const int g  = lane >> 2;
    const int t4 = lane & 3;

    float S1[4] = {0.f, 0.f, 0.f, 0.f};
    float P [4] = {0.f, 0.f, 0.f, 0.f};
    float NG[4] = {0.f, 0.f, 0.f, 0.f};

    #pragma unroll
    for (int mt = 0; mt < 2; ++mt) {
        #pragma unroll
        for (int hi = 0; hi < 2; ++hi) {
            const int ri   = mt * 2 + hi;
            const int grow = rowBase + warpM * 32 + mt * 16 + hi * 8 + g;
            const float* pmRow = pm + (size_t)grow * N;
            const float* nmRow = nm + (size_t)grow * N;
            #pragma unroll
            for (int nt = 0; nt < 8; ++nt) {
                const int gcol = colBase + warpN * 64 + nt * 8 + t4 * 2;
                float2 pv = *reinterpret_cast<const float2*>(pmRow + gcol);
                float2 nv = *reinterpret_cast<const float2*>(nmRow + gcol);
                if (grow == gcol)     { pv.x = 0.f; nv.x = 0.f; }
                if (grow == gcol + 1) { pv.y = 0.f; nv.y = 0.f; }
                const float z0 = acc[mt][nt][hi * 2 + 0] * INV_T;
                const float z1 = acc[mt][nt][hi * 2 + 1] * INV_T;
                S1[ri] += pv.x * z0 + pv.y * z1;
                P [ri] += pv.x + pv.y;
                NG[ri] += nv.x * __expf(z0) + nv.y * __expf(z1);
            }
        }
    }

    // reduce across the 4 lanes sharing each row (t4 group)
    #pragma unroll
    for (int ri = 0; ri < 4; ++ri) {
        S1[ri] += __shfl_xor_sync(0xffffffffu, S1[ri], 1);
        S1[ri] += __shfl_xor_sync(0xffffffffu, S1[ri], 2);
        P [ri] += __shfl_xor_sync(0xffffffffu, P [ri], 1);
        P [ri] += __shfl_xor_sync(0xffffffffu, P [ri], 2);
        NG[ri] += __shfl_xor_sync(0xffffffffu, NG[ri], 1);
        NG[ri] += __shfl_xor_sync(0xffffffffu, NG[ri], 2);
    }

    if (t4 == 0) {
        const int cs = blockIdx.x * 2 + warpN;
        #pragma unroll
        for (int ri = 0; ri < 4; ++ri) {
            const int mt = ri >> 1, hi = ri & 1;
            const int grow = rowBase + warpM * 32 + mt * 16 + hi * 8 + g;
            g_part[0][cs][grow] = S1[ri];
            g_part[1][cs][grow] = P[ri];
            g_part[2][cs][grow] = NG[ri];
        }
    }
}

// ---------------------------------------------------------------------------
// Kernel 3: per-row finalize + block partial sums. 16 blocks x 256 threads.
// ---------------------------------------------------------------------------
__global__ __launch_bounds__(256) void finalize_rows() {
    const int row = blockIdx.x * 256 + threadIdx.x;
    float s1 = 0.f, p = 0.f, ng = 0.f;
    #pragma unroll 8
    for (int c = 0; c < NSLOT; ++c) {
        s1 += g_part[0][c][row];
        p  += g_part[1][c][row];
        ng += g_part[2][c][row];
    }
    float term = 0.f;
    if (p > 0.5f) term = (s1 - p * logf(ng)) / p;

    __shared__ float sh[256];
    sh[threadIdx.x] = term;
    __syncthreads();
    #pragma unroll
    for (int s = 128; s > 0; s >>= 1) {
        if (threadIdx.x < s) sh[threadIdx.x] += sh[threadIdx.x + s];
        __syncthreads();
    }
    if (threadIdx.x == 0) g_bsum[blockIdx.x] = sh[0];
}

// ---------------------------------------------------------------------------
// Kernel 4: final reduction -> loss scalar.
// ---------------------------------------------------------------------------
__global__ void final_reduce(float* __restrict__ out) {
    float v = (threadIdx.x < 16) ? g_bsum[threadIdx.x] : 0.f;
    #pragma unroll
    for (int off = 8; off > 0; off >>= 1)
        v += __shfl_xor_sync(0xffffffffu, v, off);
    if (threadIdx.x == 0) out[0] = -(v / (float)N);
}

// ---------------------------------------------------------------------------
extern "C" void kernel_launch(void* const* d_in, const int* in_sizes, int n_in,
                              void* d_out, int out_size) {
    (void)in_sizes; (void)n_in; (void)out_size;
    const float* f  = (const float*)d_in[0];
    const float* pm = (const float*)d_in[1];
    const float* nm = (const float*)d_in[2];

    norm_kernel<<<N / 4, 128>>>(f);
    dim3 grid(NBLK, NBLK);
    main_kernel<<<grid, 256>>>(pm, nm);
    finalize_rows<<<16, 256>>>();
    final_reduce<<<1, 32>>>((float*)d_out);
}

// round 9
// speedup vs baseline: 1.1267x; 1.1267x over previous
#include <cuda_runtime.h>
#include <cuda_bf16.h>
#include <cstdint>

#define N 4096
#define D 256
#define NBLK 32            // 4096/128 tiles per dim
#define NSLOT 64           // 32 col-blocks * 2 n-warps
#define TILE_HW (128*72)   // halfwords per smem tile stage (stride 72)

__device__ __align__(16) __nv_bfloat16 g_fnb[(size_t)N * D];   // normalized feats bf16 (2 MB)
__device__ __align__(16) unsigned g_pmb[N][N / 32];            // pos mask bits (2 MB)
__device__ __align__(16) unsigned g_nmb[N][N / 32];            // neg mask bits (2 MB)
__device__ float g_pos[N];                                     // per-row positive counts
__device__ float g_part[2][NSLOT][N];                          // partials: S1, NEG (2 MB)
__device__ float g_bsum[16];

// ------------------------- PTX helpers -------------------------------------
__device__ __forceinline__ void ldsm_x4(unsigned &r0, unsigned &r1, unsigned &r2, unsigned &r3, unsigned addr) {
    asm volatile("ldmatrix.sync.aligned.m8n8.x4.shared.b16 {%0,%1,%2,%3}, [%4];"
                 : "=r"(r0), "=r"(r1), "=r"(r2), "=r"(r3) : "r"(addr));
}
__device__ __forceinline__ void mma_bf16(float &c0, float &c1, float &c2, float &c3,
                                         unsigned a0, unsigned a1, unsigned a2, unsigned a3,
                                         unsigned b0, unsigned b1) {
    asm volatile("mma.sync.aligned.m16n8k16.row.col.f32.bf16.bf16.f32 "
                 "{%0,%1,%2,%3},{%4,%5,%6,%7},{%8,%9},{%0,%1,%2,%3};"
                 : "+f"(c0), "+f"(c1), "+f"(c2), "+f"(c3)
                 : "r"(a0), "r"(a1), "r"(a2), "r"(a3), "r"(b0), "r"(b1));
}
#define CP16(dst, src) asm volatile("cp.async.cg.shared.global [%0], [%1], 16;" :: "r"(dst), "l"(src))
#define CPCOMMIT()     asm volatile("cp.async.commit_group;")
#define CPWAIT(n)      asm volatile("cp.async.wait_group %0;" :: "n"(n))

// ---------------------------------------------------------------------------
// Kernel A: bit-pack masks (zero diagonal) + per-row positive counts.
// One block per row; pure DRAM stream (134 MB read total).
// ---------------------------------------------------------------------------
__global__ __launch_bounds__(256) void pack_kernel(const float* __restrict__ pm,
                                                   const float* __restrict__ nm) {
    const int row  = blockIdx.x;
    const int warp = threadIdx.x >> 5;
    const int lane = threadIdx.x & 31;
    const float* pr = pm + (size_t)row * N;
    const float* nr = nm + (size_t)row * N;

    int pcnt = 0;
    #pragma unroll 4
    for (int c = warp; c < N / 32; c += 8) {
        const int col = c * 32 + lane;
        float pv = pr[col];
        float nv = nr[col];
        if (col == row) { pv = 0.f; nv = 0.f; }
        const unsigned pb = __ballot_sync(0xffffffffu, pv != 0.f);
        const unsigned nb = __ballot_sync(0xffffffffu, nv != 0.f);
        if (lane == 0) { g_pmb[row][c] = pb; g_nmb[row][c] = nb; }
        pcnt += (pv != 0.f);
    }
    #pragma unroll
    for (int off = 16; off > 0; off >>= 1)
        pcnt += __shfl_xor_sync(0xffffffffu, pcnt, off);

    __shared__ int sp[8];
    if (lane == 0) sp[warp] = pcnt;
    __syncthreads();
    if (threadIdx.x == 0) {
        int s = 0;
        #pragma unroll
        for (int i = 0; i < 8; ++i) s += sp[i];
        g_pos[row] = (float)s;
    }
}

// ---------------------------------------------------------------------------
// Kernel B: L2-normalize feature rows -> bf16. 1 warp/row.
// ---------------------------------------------------------------------------
__global__ __launch_bounds__(128) void norm_kernel(const float* __restrict__ f) {
    const int warp = threadIdx.x >> 5;
    const int lane = threadIdx.x & 31;
    const int row  = blockIdx.x * 4 + warp;

    const float4* fr = reinterpret_cast<const float4*>(f + (size_t)row * D) + lane * 2;
    float4 v0 = fr[0];
    float4 v1 = fr[1];

    float s = v0.x*v0.x + v0.y*v0.y + v0.z*v0.z + v0.w*v0.w
            + v1.x*v1.x + v1.y*v1.y + v1.z*v1.z + v1.w*v1.w;
    #pragma unroll
    for (int off = 16; off > 0; off >>= 1)
        s += __shfl_xor_sync(0xffffffffu, s, off);

    const float inv = 1.0f / fmaxf(sqrtf(s), 1e-8f);

    __nv_bfloat162 b0 = __float22bfloat162_rn(make_float2(v0.x*inv, v0.y*inv));
    __nv_bfloat162 b1 = __float22bfloat162_rn(make_float2(v0.z*inv, v0.w*inv));
    __nv_bfloat162 b2 = __float22bfloat162_rn(make_float2(v1.x*inv, v1.y*inv));
    __nv_bfloat162 b3 = __float22bfloat162_rn(make_float2(v1.z*inv, v1.w*inv));

    uint4 u;
    u.x = *reinterpret_cast<unsigned*>(&b0);
    u.y = *reinterpret_cast<unsigned*>(&b1);
    u.z = *reinterpret_cast<unsigned*>(&b2);
    u.w = *reinterpret_cast<unsigned*>(&b3);
    *reinterpret_cast<uint4*>(g_fnb + (size_t)row * D + lane * 8) = u;
}

// ---------------------------------------------------------------------------
// Kernel C: cosim GEMM (bf16 mma.sync, 2-stage cp.async pipeline) + bitmask
// epilogue. Block 128x128, 8 warps (4M x 2N), warp tile 32x64, K in 4x64.
// All inputs (g_fnb 2MB, bits 4MB) are L2-resident -> compute-bound.
// ---------------------------------------------------------------------------
extern __shared__ __align__(16) __nv_bfloat16 dynsmem[];

__global__ __launch_bounds__(256, 2) void main_kernel() {
    const int tid   = threadIdx.x;
    const int lane  = tid & 31;
    const int warp  = tid >> 5;
    const int warpM = warp >> 1;   // 0..3
    const int warpN = warp & 1;    // 0..1
    const int rowBase = blockIdx.y * 128;
    const int colBase = blockIdx.x * 128;

    float acc[2][8][4];
    #pragma unroll
    for (int i = 0; i < 2; ++i)
        #pragma unroll
        for (int j = 0; j < 8; ++j)
            #pragma unroll
            for (int k = 0; k < 4; ++k) acc[i][j][k] = 0.f;

    // copy mapping: 2 threads per tile-row, 64B (4x16B) each
    const int ldRow = tid >> 1;
    const int ldK   = (tid & 1) * 32;
    const uint4* fA = reinterpret_cast<const uint4*>(g_fnb + (size_t)(rowBase + ldRow) * D) + (ldK >> 3);
    const uint4* fB = reinterpret_cast<const uint4*>(g_fnb + (size_t)(colBase + ldRow) * D) + (ldK >> 3);

    const unsigned sBase = (unsigned)__cvta_generic_to_shared(dynsmem);
    const unsigned sA0 = sBase;                       // stages 0,1
    const unsigned sB0 = sBase + 2 * TILE_HW * 2;     // stages 0,1
    const unsigned dstA = sA0 + (ldRow * 72 + ldK) * 2;
    const unsigned dstB = sB0 + (ldRow * 72 + ldK) * 2;

#define PREFETCH(kb, s) do {                                            \
        unsigned da = dstA + (s) * TILE_HW * 2;                         \
        unsigned db = dstB + (s) * TILE_HW * 2;                         \
        const uint4* pa = fA + (kb) * 8;                                \
        const uint4* pb = fB + (kb) * 8;                                \
        CP16(da +  0, pa + 0); CP16(db +  0, pb + 0);                   \
        CP16(da + 16, pa + 1); CP16(db + 16, pb + 1);                   \
        CP16(da + 32, pa + 2); CP16(db + 32, pb + 2);                   \
        CP16(da + 48, pa + 3); CP16(db + 48, pb + 3);                   \
        CPCOMMIT();                                                     \
    } while (0)

    // ldmatrix per-lane address components
    const int aRow = (lane & 7) + ((lane & 8)  ? 8 : 0);
    const int aK8  = (lane & 16) ? 8 : 0;
    const int bRow = (lane & 7) + ((lane & 16) ? 8 : 0);
    const int bK8  = (lane & 8)  ? 8 : 0;

    PREFETCH(0, 0);
    PREFETCH(1, 1);

    #pragma unroll
    for (int kb = 0; kb < 4; ++kb) {
        if (kb == 3) { CPWAIT(0); } else { CPWAIT(1); }
        __syncthreads();

        const unsigned sA = sA0 + (kb & 1) * TILE_HW * 2;
        const unsigned sB = sB0 + (kb & 1) * TILE_HW * 2;

        #pragma unroll
        for (int kk = 0; kk < 4; ++kk) {
            unsigned b[4][4];
            #pragma unroll
            for (int p = 0; p < 4; ++p) {
                unsigned addr = sB + ((warpN * 64 + p * 16 + bRow) * 72 + kk * 16 + bK8) * 2;
                ldsm_x4(b[p][0], b[p][1], b[p][2], b[p][3], addr);
            }
            unsigned a[2][4];
            #pragma unroll
            for (int mt = 0; mt < 2; ++mt) {
                unsigned addr = sA + ((warpM * 32 + mt * 16 + aRow) * 72 + kk * 16 + aK8) * 2;
                ldsm_x4(a[mt][0], a[mt][1], a[mt][2], a[mt][3], addr);
            }
            #pragma unroll
            for (int mt = 0; mt < 2; ++mt)
                #pragma unroll
                for (int p = 0; p < 4; ++p) {
                    mma_bf16(acc[mt][2*p  ][0], acc[mt][2*p  ][1], acc[mt][2*p  ][2], acc[mt][2*p  ][3],
                             a[mt][0], a[mt][1], a[mt][2], a[mt][3], b[p][0], b[p][1]);
                    mma_bf16(acc[mt][2*p+1][0], acc[mt][2*p+1][1], acc[mt][2*p+1][2], acc[mt][2*p+1][3],
                             a[mt][0], a[mt][1], a[mt][2], a[mt][3], b[p][2], b[p][3]);
                }
        }
        __syncthreads();
        if (kb < 2) {
            if (kb == 0) PREFETCH(2, 0); else PREFETCH(3, 1);
        }
    }
#undef PREFETCH

    // ---- epilogue: bitmask words from L2, accumulate per-row S1 / NEG ----
    const float INV_T = 1.0f / 0.07f;
    const int g  = lane >> 2;
    const int t4 = lane & 3;
    const int w0 = (colBase + warpN * 64) >> 5;  // even -> uint2-aligned

    float S1[4] = {0.f, 0.f, 0.f, 0.f};
    float NG[4] = {0.f, 0.f, 0.f, 0.f};

    #pragma unroll
    for (int mt = 0; mt < 2; ++mt) {
        #pragma unroll
        for (int hi = 0; hi < 2; ++hi) {
            const int ri   = mt * 2 + hi;
            const int grow = rowBase + warpM * 32 + mt * 16 + hi * 8 + g;
            const uint2 pw = *reinterpret_cast<const uint2*>(&g_pmb[grow][w0]);
            const uint2 nw = *reinterpret_cast<const uint2*>(&g_nmb[grow][w0]);
            #pragma unroll
            for (int nt = 0; nt < 8; ++nt) {
                const unsigned pword = (nt < 4) ? pw.x : pw.y;
                const unsigned nword = (nt < 4) ? nw.x : nw.y;
                const int bit = t4 * 2 + (nt & 3) * 8;
                const float z0 = acc[mt][nt][hi * 2 + 0] * INV_T;
                const float z1 = acc[mt][nt][hi * 2 + 1] * INV_T;
                const float p0 = (float)((pword >> bit) & 1u);
                const float p1 = (float)((pword >> (bit + 1)) & 1u);
                const float n0 = (float)((nword >> bit) & 1u);
                const float n1 = (float)((nword >> (bit + 1)) & 1u);
                S1[ri] += p0 * z0 + p1 * z1;
                NG[ri] += n0 * __expf(z0) + n1 * __expf(z1);
            }
        }
    }

    #pragma unroll
    for (int ri = 0; ri < 4; ++ri) {
        S1[ri] += __shfl_xor_sync(0xffffffffu, S1[ri], 1);
        S1[ri] += __shfl_xor_sync(0xffffffffu, S1[ri], 2);
        NG[ri] += __shfl_xor_sync(0xffffffffu, NG[ri], 1);
        NG[ri] += __shfl_xor_sync(0xffffffffu, NG[ri], 2);
    }

    if (t4 == 0) {
        const int cs = blockIdx.x * 2 + warpN;
        #pragma unroll
        for (int ri = 0; ri < 4; ++ri) {
            const int mt = ri >> 1, hi = ri & 1;
            const int grow = rowBase + warpM * 32 + mt * 16 + hi * 8 + g;
            g_part[0][cs][grow] = S1[ri];
            g_part[1][cs][grow] = NG[ri];
        }
    }
}

// ---------------------------------------------------------------------------
// Kernel D: per-row finalize + block partial sums.
// ---------------------------------------------------------------------------
__global__ __launch_bounds__(256) void finalize_rows() {
    const int row = blockIdx.x * 256 + threadIdx.x;
    float s1 = 0.f, ng = 0.f;
    #pragma unroll 8
    for (int c = 0; c < NSLOT; ++c) {
        s1 += g_part[0][c][row];
        ng += g_part[1][c][row];
    }
    const float p = g_pos[row];
    float term = 0.f;
    if (p > 0.5f) term = (s1 - p * logf(ng)) / p;

    __shared__ float sh[256];
    sh[threadIdx.x] = term;
    __syncthreads();
    #pragma unroll
    for (int s = 128; s > 0; s >>= 1) {
        if (threadIdx.x < s) sh[threadIdx.x] += sh[threadIdx.x + s];
        __syncthreads();
    }
    if (threadIdx.x == 0) g_bsum[blockIdx.x] = sh[0];
}

// ---------------------------------------------------------------------------
// Kernel E: final reduction -> -mean.
// ---------------------------------------------------------------------------
__global__ void final_reduce(float* __restrict__ out) {
    float v = (threadIdx.x < 16) ? g_bsum[threadIdx.x] : 0.f;
    #pragma unroll
    for (int off = 8; off > 0; off >>= 1)
        v += __shfl_xor_sync(0xffffffffu, v, off);
    if (threadIdx.x == 0) out[0] = -(v / (float)N);
}

// ---------------------------------------------------------------------------
extern "C" void kernel_launch(void* const* d_in, const int* in_sizes, int n_in,
                              void* d_out, int out_size) {
    (void)in_sizes; (void)n_in; (void)out_size;
    const float* f  = (const float*)d_in[0];
    const float* pm = (const float*)d_in[1];
    const float* nm = (const float*)d_in[2];

    static bool attr_set = false;
    if (!attr_set) {
        cudaFuncSetAttribute(main_kernel, cudaFuncAttributeMaxDynamicSharedMemorySize,
                             4 * TILE_HW * 2);
        attr_set = true;
    }

    pack_kernel<<<N, 256>>>(pm, nm);        // stream masks (DRAM-bound)
    norm_kernel<<<N / 4, 128>>>(f);         // keep g_fnb hot in L2 right before GEMM
    dim3 grid(NBLK, NBLK);
    main_kernel<<<grid, 256, 4 * TILE_HW * 2>>>();
    finalize_rows<<<16, 256>>>();
    final_reduce<<<1, 32>>>((float*)d_out);
}

// round 10
// speedup vs baseline: 1.3830x; 1.2275x over previous
#include <cuda_runtime.h>
#include <cuda_bf16.h>
#include <cstdint>

#define N 4096
#define D 256
#define NBLK 32            // 4096/128 tiles per dim
#define NSLOT 64           // 32 col-blocks * 2 n-warps
#define TILE_HW (128*72)   // halfwords per smem tile stage (stride 72)

__device__ __align__(16) __nv_bfloat16 g_fnb[(size_t)N * D];   // normalized feats bf16 (2 MB)
__device__ float g_part[3][NSLOT][N];                          // partials: S1, P, NEG (3 MB)
__device__ float g_bsum[64];

// ------------------------- PTX helpers -------------------------------------
__device__ __forceinline__ void ldsm_x4(unsigned &r0, unsigned &r1, unsigned &r2, unsigned &r3, unsigned addr) {
    asm volatile("ldmatrix.sync.aligned.m8n8.x4.shared.b16 {%0,%1,%2,%3}, [%4];"
                 : "=r"(r0), "=r"(r1), "=r"(r2), "=r"(r3) : "r"(addr));
}
__device__ __forceinline__ void mma_bf16(float &c0, float &c1, float &c2, float &c3,
                                         unsigned a0, unsigned a1, unsigned a2, unsigned a3,
                                         unsigned b0, unsigned b1) {
    asm volatile("mma.sync.aligned.m16n8k16.row.col.f32.bf16.bf16.f32 "
                 "{%0,%1,%2,%3},{%4,%5,%6,%7},{%8,%9},{%0,%1,%2,%3};"
                 : "+f"(c0), "+f"(c1), "+f"(c2), "+f"(c3)
                 : "r"(a0), "r"(a1), "r"(a2), "r"(a3), "r"(b0), "r"(b1));
}
#define CP16(dst, src) asm volatile("cp.async.cg.shared.global [%0], [%1], 16;" :: "r"(dst), "l"(src))
#define CPCOMMIT()     asm volatile("cp.async.commit_group;")
#define CPWAIT(n)      asm volatile("cp.async.wait_group %0;" :: "n"(n))

// ---------------------------------------------------------------------------
// Kernel B: L2-normalize feature rows -> bf16. 1 warp/row.
// ---------------------------------------------------------------------------
__global__ __launch_bounds__(128) void norm_kernel(const float* __restrict__ f) {
    const int warp = threadIdx.x >> 5;
    const int lane = threadIdx.x & 31;
    const int row  = blockIdx.x * 4 + warp;

    const float4* fr = reinterpret_cast<const float4*>(f + (size_t)row * D) + lane * 2;
    float4 v0 = fr[0];
    float4 v1 = fr[1];

    float s = v0.x*v0.x + v0.y*v0.y + v0.z*v0.z + v0.w*v0.w
            + v1.x*v1.x + v1.y*v1.y + v1.z*v1.z + v1.w*v1.w;
    #pragma unroll
    for (int off = 16; off > 0; off >>= 1)
        s += __shfl_xor_sync(0xffffffffu, s, off);

    const float inv = 1.0f / fmaxf(sqrtf(s), 1e-8f);

    __nv_bfloat162 b0 = __float22bfloat162_rn(make_float2(v0.x*inv, v0.y*inv));
    __nv_bfloat162 b1 = __float22bfloat162_rn(make_float2(v0.z*inv, v0.w*inv));
    __nv_bfloat162 b2 = __float22bfloat162_rn(make_float2(v1.x*inv, v1.y*inv));
    __nv_bfloat162 b3 = __float22bfloat162_rn(make_float2(v1.z*inv, v1.w*inv));

    uint4 u;
    u.x = *reinterpret_cast<unsigned*>(&b0);
    u.y = *reinterpret_cast<unsigned*>(&b1);
    u.z = *reinterpret_cast<unsigned*>(&b2);
    u.w = *reinterpret_cast<unsigned*>(&b3);
    *reinterpret_cast<uint4*>(g_fnb + (size_t)row * D + lane * 8) = u;
}

// ---------------------------------------------------------------------------
// Kernel C: cosim GEMM (bf16 mma.sync, 2-stage cp.async pipeline) + fused
// float-mask streaming epilogue (masks read exactly once, here).
// Block 128x128, 8 warps (4M x 2N), warp tile 32x64, K in 4x64.
// ---------------------------------------------------------------------------
extern __shared__ __align__(16) __nv_bfloat16 dynsmem[];

__global__ __launch_bounds__(256, 2) void main_kernel(const float* __restrict__ pm,
                                                      const float* __restrict__ nm) {
    const int tid   = threadIdx.x;
    const int lane  = tid & 31;
    const int warp  = tid >> 5;
    const int warpM = warp >> 1;   // 0..3
    const int warpN = warp & 1;    // 0..1
    const int rowBase = blockIdx.y * 128;
    const int colBase = blockIdx.x * 128;

    float acc[2][8][4];
    #pragma unroll
    for (int i = 0; i < 2; ++i)
        #pragma unroll
        for (int j = 0; j < 8; ++j)
            #pragma unroll
            for (int k = 0; k < 4; ++k) acc[i][j][k] = 0.f;

    // copy mapping: 2 threads per tile-row, 64B (4x16B) each
    const int ldRow = tid >> 1;
    const int ldK   = (tid & 1) * 32;
    const uint4* fA = reinterpret_cast<const uint4*>(g_fnb + (size_t)(rowBase + ldRow) * D) + (ldK >> 3);
    const uint4* fB = reinterpret_cast<const uint4*>(g_fnb + (size_t)(colBase + ldRow) * D) + (ldK >> 3);

    const unsigned sBase = (unsigned)__cvta_generic_to_shared(dynsmem);
    const unsigned sA0 = sBase;                       // stages 0,1
    const unsigned sB0 = sBase + 2 * TILE_HW * 2;     // stages 0,1
    const unsigned dstA = sA0 + (ldRow * 72 + ldK) * 2;
    const unsigned dstB = sB0 + (ldRow * 72 + ldK) * 2;

#define PREFETCH(kb, s) do {                                            \
        unsigned da = dstA + (s) * TILE_HW * 2;                         \
        unsigned db = dstB + (s) * TILE_HW * 2;                         \
        const uint4* pa = fA + (kb) * 8;                                \
        const uint4* pb = fB + (kb) * 8;                                \
        CP16(da +  0, pa + 0); CP16(db +  0, pb + 0);                   \
        CP16(da + 16, pa + 1); CP16(db + 16, pb + 1);                   \
        CP16(da + 32, pa + 2); CP16(db + 32, pb + 2);                   \
        CP16(da + 48, pa + 3); CP16(db + 48, pb + 3);                   \
        CPCOMMIT();                                                     \
    } while (0)

    // ldmatrix per-lane address components
    const int aRow = (lane & 7) + ((lane & 8)  ? 8 : 0);
    const int aK8  = (lane & 16) ? 8 : 0;
    const int bRow = (lane & 7) + ((lane & 16) ? 8 : 0);
    const int bK8  = (lane & 8)  ? 8 : 0;

    PREFETCH(0, 0);
    PREFETCH(1, 1);

    #pragma unroll
    for (int kb = 0; kb < 4; ++kb) {
        if (kb == 3) { CPWAIT(0); } else { CPWAIT(1); }
        __syncthreads();

        const unsigned sA = sA0 + (kb & 1) * TILE_HW * 2;
        const unsigned sB = sB0 + (kb & 1) * TILE_HW * 2;

        #pragma unroll
        for (int kk = 0; kk < 4; ++kk) {
            unsigned b[4][4];
            #pragma unroll
            for (int p = 0; p < 4; ++p) {
                unsigned addr = sB + ((warpN * 64 + p * 16 + bRow) * 72 + kk * 16 + bK8) * 2;
                ldsm_x4(b[p][0], b[p][1], b[p][2], b[p][3], addr);
            }
            unsigned a[2][4];
            #pragma unroll
            for (int mt = 0; mt < 2; ++mt) {
                unsigned addr = sA + ((warpM * 32 + mt * 16 + aRow) * 72 + kk * 16 + aK8) * 2;
                ldsm_x4(a[mt][0], a[mt][1], a[mt][2], a[mt][3], addr);
            }
            #pragma unroll
            for (int mt = 0; mt < 2; ++mt)
                #pragma unroll
                for (int p = 0; p < 4; ++p) {
                    mma_bf16(acc[mt][2*p  ][0], acc[mt][2*p  ][1], acc[mt][2*p  ][2], acc[mt][2*p  ][3],
                             a[mt][0], a[mt][1], a[mt][2], a[mt][3], b[p][0], b[p][1]);
                    mma_bf16(acc[mt][2*p+1][0], acc[mt][2*p+1][1], acc[mt][2*p+1][2], acc[mt][2*p+1][3],
                             a[mt][0], a[mt][1], a[mt][2], a[mt][3], b[p][2], b[p][3]);
                }
        }
        __syncthreads();
        if (kb < 2) {
            if (kb == 0) PREFETCH(2, 0); else PREFETCH(3, 1);
        }
    }
#undef PREFETCH

    // ---- epilogue: stream float masks once, accumulate per-row S1 / P / NEG ----
    const float INV_T = 1.0f / 0.07f;
    const int g  = lane >> 2;
    const int t4 = lane & 3;

    float S1[4] = {0.f, 0.f, 0.f, 0.f};
    float P [4] = {0.f, 0.f, 0.f, 0.f};
    float NG[4] = {0.f, 0.f, 0.f, 0.f};

    #pragma unroll
    for (int mt = 0; mt < 2; ++mt) {
        #pragma unroll
        for (int hi = 0; hi < 2; ++hi) {
            const int ri   = mt * 2 + hi;
            const int grow = rowBase + warpM * 32 + mt * 16 + hi * 8 + g;
            const float* pmRow = pm + (size_t)grow * N;
            const float* nmRow = nm + (size_t)grow * N;
            // issue all 16 loads first (MLP), then math
            float2 pv[8], nv[8];
            #pragma unroll
            for (int nt = 0; nt < 8; ++nt) {
                const int gcol = colBase + warpN * 64 + nt * 8 + t4 * 2;
                pv[nt] = *reinterpret_cast<const float2*>(pmRow + gcol);
                nv[nt] = *reinterpret_cast<const float2*>(nmRow + gcol);
            }
            #pragma unroll
            for (int nt = 0; nt < 8; ++nt) {
                const int gcol = colBase + warpN * 64 + nt * 8 + t4 * 2;
                float p0 = pv[nt].x, p1 = pv[nt].y;
                float n0 = nv[nt].x, n1 = nv[nt].y;
                if (grow == gcol)     { p0 = 0.f; n0 = 0.f; }
                if (grow == gcol + 1) { p1 = 0.f; n1 = 0.f; }
                const float z0 = acc[mt][nt][hi * 2 + 0] * INV_T;
                const float z1 = acc[mt][nt][hi * 2 + 1] * INV_T;
                S1[ri] += p0 * z0 + p1 * z1;
                P [ri] += p0 + p1;
                NG[ri] += n0 * __expf(z0) + n1 * __expf(z1);
            }
        }
    }

    // reduce across the 4 lanes sharing each row
    #pragma unroll
    for (int ri = 0; ri < 4; ++ri) {
        S1[ri] += __shfl_xor_sync(0xffffffffu, S1[ri], 1);
        S1[ri] += __shfl_xor_sync(0xffffffffu, S1[ri], 2);
        P [ri] += __shfl_xor_sync(0xffffffffu, P [ri], 1);
        P [ri] += __shfl_xor_sync(0xffffffffu, P [ri], 2);
        NG[ri] += __shfl_xor_sync(0xffffffffu, NG[ri], 1);
        NG[ri] += __shfl_xor_sync(0xffffffffu, NG[ri], 2);
    }

    if (t4 == 0) {
        const int cs = blockIdx.x * 2 + warpN;
        #pragma unroll
        for (int ri = 0; ri < 4; ++ri) {
            const int mt = ri >> 1, hi = ri & 1;
            const int grow = rowBase + warpM * 32 + mt * 16 + hi * 8 + g;
            g_part[0][cs][grow] = S1[ri];
            g_part[1][cs][grow] = P[ri];
            g_part[2][cs][grow] = NG[ri];
        }
    }
}

// ---------------------------------------------------------------------------
// Kernel D: per-row finalize + block partial sums.
// 64 blocks x 256 threads: 64 rows/block, 4 slot-groups of 16 per row.
// Coalesced 64-thread row stripes; smem combine across slot-groups.
// ---------------------------------------------------------------------------
__global__ __launch_bounds__(256) void finalize_rows() {
    const int r   = threadIdx.x & 63;          // row within block
    const int p   = threadIdx.x >> 6;          // slot group 0..3
    const int row = blockIdx.x * 64 + r;

    float s1 = 0.f, pp = 0.f, ng = 0.f;
    #pragma unroll
    for (int c = p * 16; c < p * 16 + 16; ++c) {
        s1 += g_part[0][c][row];
        pp += g_part[1][c][row];
        ng += g_part[2][c][row];
    }

    __shared__ float sh[3][4][64];
    sh[0][p][r] = s1; sh[1][p][r] = pp; sh[2][p][r] = ng;
    __syncthreads();

    __shared__ float st[64];
    if (p == 0) {
        s1 = sh[0][0][r] + sh[0][1][r] + sh[0][2][r] + sh[0][3][r];
        pp = sh[1][0][r] + sh[1][1][r] + sh[1][2][r] + sh[1][3][r];
        ng = sh[2][0][r] + sh[2][1][r] + sh[2][2][r] + sh[2][3][r];
        float term = 0.f;
        if (pp > 0.5f) term = (s1 - pp * logf(ng)) / pp;
        st[r] = term;
    }
    __syncthreads();
    if (threadIdx.x < 32) {
        float v = st[threadIdx.x] + st[threadIdx.x + 32];
        #pragma unroll
        for (int off = 16; off > 0; off >>= 1)
            v += __shfl_xor_sync(0xffffffffu, v, off);
        if (threadIdx.x == 0) g_bsum[blockIdx.x] = v;
    }
}

// ---------------------------------------------------------------------------
// Kernel E: final reduction -> -mean.
// ---------------------------------------------------------------------------
__global__ void final_reduce(float* __restrict__ out) {
    float v = g_bsum[threadIdx.x] + g_bsum[threadIdx.x + 32];
    #pragma unroll
    for (int off = 16; off > 0; off >>= 1)
        v += __shfl_xor_sync(0xffffffffu, v, off);
    if (threadIdx.x == 0) out[0] = -(v / (float)N);
}

// ---------------------------------------------------------------------------
extern "C" void kernel_launch(void* const* d_in, const int* in_sizes, int n_in,
                              void* d_out, int out_size) {
    (void)in_sizes; (void)n_in; (void)out_size;
    const float* f  = (const float*)d_in[0];
    const float* pm = (const float*)d_in[1];
    const float* nm = (const float*)d_in[2];

    static bool attr_set = false;
    if (!attr_set) {
        cudaFuncSetAttribute(main_kernel, cudaFuncAttributeMaxDynamicSharedMemorySize,
                             4 * TILE_HW * 2);
        attr_set = true;
    }

    norm_kernel<<<N / 4, 128>>>(f);
    dim3 grid(NBLK, NBLK);
    main_kernel<<<grid, 256, 4 * TILE_HW * 2>>>(pm, nm);
    finalize_rows<<<64, 256>>>();
    final_reduce<<<1, 32>>>((float*)d_out);
}